// round 1
// baseline (speedup 1.0000x reference)
#include <cuda_runtime.h>
#include <cstdint>
#include <math.h>

typedef unsigned long long ull;
typedef unsigned int uint;

#define C_DIM 512
#define NE 256
#define HW 4096
#define NTOK 65536
#define NBLK 512  /* NTOK / 128 tokens per block */

// -------- scratch (static device globals; no runtime allocation) --------
__device__ float g_wT[C_DIM * NE];    // wT[c][j] scaled codebook, transposed
__device__ float g_n[NE];             // ||w_j||^2
__device__ float g_pwT[C_DIM * NE];   // pwT[o][j] = conv_w[o].w_j + b[o]
__device__ int   g_hist[NE];
__device__ float g_partial[NBLK];

// ---------------- helpers ----------------
__device__ __forceinline__ ull pack2(float lo, float hi) {
    ull r;
    asm("mov.b64 %0, {%1, %2};" : "=l"(r) : "f"(lo), "f"(hi));
    return r;
}

__device__ __forceinline__ void get_scalars(const float* stdp, const float* means,
                                            float& s, float& m) {
    s = fabsf(stdp[0]);
    m = __fdiv_rn(means[0] + means[1] + means[2], 3.0f);
}

// ---------------- init ----------------
__global__ void k_init() {
    int t = threadIdx.x;
    if (t < NE)   g_hist[t] = 0;
    if (t < NBLK) g_partial[t] = 0.f;
}

// ---------------- prep: scaled codebook (transposed) ----------------
__global__ void k_prep_w(const float* __restrict__ emb,
                         const float* __restrict__ stdp,
                         const float* __restrict__ means) {
    int c = blockIdx.x, j = threadIdx.x;
    float s, m;
    get_scalars(stdp, means, s, m);
    float e = emb[(size_t)j * C_DIM + c];
    // mimic reference elementwise: fl(fl(e*std)+mean)
    g_wT[c * NE + j] = __fadd_rn(__fmul_rn(e, s), m);
}

// ---------------- prep: code norms ----------------
__global__ void k_prep_n() {
    int j = threadIdx.x;
    float a = 0.f;
    for (int c = 0; c < C_DIM; c++) {
        float v = g_wT[c * NE + j];
        a = fmaf(v, v, a);
    }
    g_n[j] = a;
}

// ---------------- prep: projected codebook pwT[o][j] ----------------
__global__ void k_prep_pw(const float* __restrict__ convw,
                          const float* __restrict__ convb) {
    __shared__ float cw[16][512];   // 32 KB
    int bo = blockIdx.x * 16;       // 16 output channels per block
    for (int p = 0; p < 32; p++) {
        int id = threadIdx.x + p * 256;           // 0..8191
        cw[id >> 9][id & 511] = convw[(size_t)bo * 512 + id];
    }
    __syncthreads();
    int j = threadIdx.x;
    float acc[16];
#pragma unroll
    for (int o = 0; o < 16; o++) acc[o] = 0.f;
    for (int c = 0; c < C_DIM; c++) {
        float wv = g_wT[c * NE + j];
#pragma unroll
        for (int o = 0; o < 16; o++) acc[o] = fmaf(cw[o][c], wv, acc[o]);
    }
#pragma unroll
    for (int o = 0; o < 16; o++)
        g_pwT[(size_t)(bo + o) * NE + j] = __fadd_rn(acc[o], convb[bo + o]);
}

// ---------------- main fused kernel ----------------
// Block: 128 tokens x 256 codes. 512 threads = 16 warps.
// warp ty owns tokens ty*8..ty*8+7; lane tx owns codes {tx*4..tx*4+3, 128+tx*4..+3}.
__global__ __launch_bounds__(512, 1) void k_main(const float* __restrict__ z,
                                                 float* __restrict__ out) {
    __shared__ union SM {
        struct { float zs[2][16][128]; float ws[2][16][256]; } g;   // 49152 B
        struct { float pws[32 * 256]; int idx[128]; float A[128];
                 float dsum[16]; int hist[256]; } p;                // ~35 KB
    } S;

    const int tid = threadIdx.x;
    const int tx = tid & 31, ty = tid >> 5;
    const int b = blockIdx.x >> 5;            // 32 blocks per batch image
    const int hw0 = (blockIdx.x & 31) << 7;   // 128 hw positions
    const float* zb = z + (size_t)b * C_DIM * HW + hw0;

    ull acc[8][4];
#pragma unroll
    for (int t = 0; t < 8; t++)
#pragma unroll
        for (int p = 0; p < 4; p++) acc[t][p] = 0ull;

    float regA = 0.f;   // per-token ||z||^2 partial (threads 0..127)

    // ---- prologue: load stage 0 ----
    float4 pz, pw0, pw1;
    pz  = *(const float4*)(zb + (size_t)ty * HW + tx * 4);
    {
        int id0 = tid, id1 = tid + 512;
        pw0 = *(const float4*)(g_wT + (size_t)(id0 >> 6) * NE + (id0 & 63) * 4);
        pw1 = *(const float4*)(g_wT + (size_t)(id1 >> 6) * NE + (id1 & 63) * 4);
    }
    *(float4*)&S.g.zs[0][ty][tx * 4] = pz;
    {
        int id0 = tid, id1 = tid + 512;
        *(float4*)&S.g.ws[0][id0 >> 6][(id0 & 63) * 4] = pw0;
        *(float4*)&S.g.ws[0][id1 >> 6][(id1 & 63) * 4] = pw1;
    }

    // ---- K loop: 32 stages of Kc=16, double buffered ----
    for (int s = 0; s < 32; s++) {
        int buf = s & 1;
        if (s < 31) {
            int c0 = (s + 1) * 16;
            pz = *(const float4*)(zb + (size_t)(c0 + ty) * HW + tx * 4);
            int id0 = tid, id1 = tid + 512;
            pw0 = *(const float4*)(g_wT + (size_t)(c0 + (id0 >> 6)) * NE + (id0 & 63) * 4);
            pw1 = *(const float4*)(g_wT + (size_t)(c0 + (id1 >> 6)) * NE + (id1 & 63) * 4);
        }
        __syncthreads();
#pragma unroll
        for (int k = 0; k < 16; k++) {
            float4 za = *(const float4*)&S.g.zs[buf][k][ty * 8];
            float4 zc = *(const float4*)&S.g.zs[buf][k][ty * 8 + 4];
            float4 wa = *(const float4*)&S.g.ws[buf][k][tx * 4];
            float4 wb = *(const float4*)&S.g.ws[buf][k][128 + tx * 4];
            ull wp[4];
            wp[0] = pack2(wa.x, wa.y); wp[1] = pack2(wa.z, wa.w);
            wp[2] = pack2(wb.x, wb.y); wp[3] = pack2(wb.z, wb.w);
            float zt[8] = {za.x, za.y, za.z, za.w, zc.x, zc.y, zc.z, zc.w};
#pragma unroll
            for (int t = 0; t < 8; t++) {
                ull zz = pack2(zt[t], zt[t]);
#pragma unroll
                for (int p = 0; p < 4; p++)
                    asm("fma.rn.f32x2 %0, %1, %2, %0;"
                        : "+l"(acc[t][p]) : "l"(zz), "l"(wp[p]));
            }
        }
        if (tid < 128) {   // warps 0-3: accumulate ||z||^2 per token
#pragma unroll
            for (int k = 0; k < 16; k++) {
                float v = S.g.zs[buf][k][tid];
                regA = fmaf(v, v, regA);
            }
        }
        if (s < 31) {
            int nb = buf ^ 1;
            *(float4*)&S.g.zs[nb][ty][tx * 4] = pz;
            int id0 = tid, id1 = tid + 512;
            *(float4*)&S.g.ws[nb][id0 >> 6][(id0 & 63) * 4] = pw0;
            *(float4*)&S.g.ws[nb][id1 >> 6][(id1 & 63) * 4] = pw1;
        }
    }
    __syncthreads();

    // ---- phase 2: argmin + loss + histogram ----
    if (tid < 128) S.p.A[tid] = regA;
    if (tid < 256) S.p.hist[tid] = 0;
    __syncthreads();

    float dloc = 0.f;
#pragma unroll
    for (int t = 0; t < 8; t++) {
        int tok = ty * 8 + t;
        float At = S.p.A[tok];
        float bd = __int_as_float(0x7f800000);  // +inf
        int bi = 0;
#pragma unroll
        for (int p = 0; p < 4; p++) {
            int cb = (p < 2) ? (tx * 4 + 2 * p) : (128 + tx * 4 + 2 * (p - 2));
            float dot0 = __uint_as_float((uint)(acc[t][p] & 0xffffffffull));
            float dot1 = __uint_as_float((uint)(acc[t][p] >> 32));
            // mimic reference: fl(fl(A + n_j) - 2*dot)
            float n0 = __ldg(&g_n[cb]);
            float n1 = __ldg(&g_n[cb + 1]);
            float d0 = __fadd_rn(__fadd_rn(At, n0), -2.0f * dot0);
            float d1 = __fadd_rn(__fadd_rn(At, n1), -2.0f * dot1);
            if (d0 < bd) { bd = d0; bi = cb; }
            if (d1 < bd) { bd = d1; bi = cb + 1; }
        }
#pragma unroll
        for (int off = 16; off > 0; off >>= 1) {
            float od = __shfl_xor_sync(0xffffffffu, bd, off);
            int   oi = __shfl_xor_sync(0xffffffffu, bi, off);
            if (od < bd || (od == bd && oi < bi)) { bd = od; bi = oi; }
        }
        if (tx == 0) {
            S.p.idx[tok] = bi;
            atomicAdd(&S.p.hist[bi], 1);
            dloc += bd;
        }
    }
    if (tx == 0) S.p.dsum[ty] = dloc;
    __syncthreads();
    if (tid == 0) {
        float sum = 0.f;
#pragma unroll
        for (int i = 0; i < 16; i++) sum += S.p.dsum[i];
        g_partial[blockIdx.x] = sum;   // deterministic: direct store per block
    }
    if (tid < 256) atomicAdd(&g_hist[tid], S.p.hist[tid]);  // int atomics: deterministic

    // ---- phase 3: gather projected codebook -> output ----
    const size_t outbase = (size_t)b * C_DIM * HW + hw0;
    for (int ch = 0; ch < 16; ch++) {     // 32 output channels per chunk
        __syncthreads();
#pragma unroll
        for (int p = 0; p < 4; p++) {
            int id = tid + p * 512;       // 0..2047 float4s
            *(float4*)&S.p.pws[(id >> 6) * NE + (id & 63) * 4] =
                *(const float4*)&g_pwT[(size_t)(ch * 32 + (id >> 6)) * NE + (id & 63) * 4];
        }
        __syncthreads();
        int i = tid & 127, og = tid >> 7;
        int mi = S.p.idx[i];
#pragma unroll
        for (int r = 0; r < 8; r++) {
            int ol = og * 8 + r;
            out[outbase + (size_t)(ch * 32 + ol) * HW + i] = S.p.pws[ol * NE + mi];
        }
    }
}

// ---------------- finalize: loss + perplexity ----------------
__global__ void k_fin(float* __restrict__ out, long long osize) {
    if (threadIdx.x == 0) {
        float s = 0.f;
        for (int i = 0; i < NBLK; i++) s += g_partial[i];
        float m = s * (1.0f / 33554432.0f);        // exact power-of-two scale
        out[osize - 2] = __fadd_rn(m, 0.25f * m);  // mean + BETA*mean
        float h = 0.f;
        for (int j = 0; j < NE; j++) {
            float e = (float)g_hist[j] * (1.0f / 65536.0f);
            h += e * logf(e + 1e-10f);
        }
        out[osize - 1] = expf(-h);
    }
}

// ---------------- launch ----------------
extern "C" void kernel_launch(void* const* d_in, const int* in_sizes, int n_in,
                              void* d_out, int out_size) {
    const float* z     = (const float*)d_in[0];
    const float* emb   = (const float*)d_in[1];
    const float* stdp  = (const float*)d_in[2];
    const float* means = (const float*)d_in[3];
    const float* convw = (const float*)d_in[4];
    const float* convb = (const float*)d_in[5];
    float* out = (float*)d_out;

    k_init<<<1, 512>>>();
    k_prep_w<<<512, 256>>>(emb, stdp, means);
    k_prep_n<<<1, 256>>>();
    k_prep_pw<<<32, 256>>>(convw, convb);
    k_main<<<NBLK, 512>>>(z, out);
    k_fin<<<1, 32>>>(out, (long long)out_size);
}

// round 2
// speedup vs baseline: 1.1322x; 1.1322x over previous
#include <cuda_runtime.h>
#include <cstdint>
#include <math.h>

typedef unsigned long long ull;
typedef unsigned int uint;

#define C_DIM 512
#define NE 256
#define HW 4096
#define NTOK 65536
#define NBLK 512  /* NTOK / 128 tokens per block */

// -------- scratch (static device globals; no runtime allocation) --------
__device__ float g_wT[C_DIM * NE];    // wT[c][j] scaled codebook, transposed
__device__ float g_n[NE];             // ||w_j||^2
__device__ float g_pwT[C_DIM * NE];   // pwT[o][j] = conv_w[o].w_j + b[o]
__device__ int   g_hist[NE];
__device__ float g_partial[NBLK];

// ---------------- helpers ----------------
__device__ __forceinline__ ull pack2(float lo, float hi) {
    ull r;
    asm("mov.b64 %0, {%1, %2};" : "=l"(r) : "f"(lo), "f"(hi));
    return r;
}

__device__ __forceinline__ void get_scalars(const float* stdp, const float* means,
                                            float& s, float& m) {
    s = fabsf(stdp[0]);
    m = __fdiv_rn(means[0] + means[1] + means[2], 3.0f);
}

// ---------------- init ----------------
__global__ void k_init() {
    int t = threadIdx.x;
    if (t < NE)   g_hist[t] = 0;
    if (t < NBLK) g_partial[t] = 0.f;
}

// ---------------- prep: scaled codebook (transposed) ----------------
__global__ void k_prep_w(const float* __restrict__ emb,
                         const float* __restrict__ stdp,
                         const float* __restrict__ means) {
    int c = blockIdx.x, j = threadIdx.x;
    float s, m;
    get_scalars(stdp, means, s, m);
    float e = emb[(size_t)j * C_DIM + c];
    // mimic reference elementwise: fl(fl(e*std)+mean)
    g_wT[c * NE + j] = __fadd_rn(__fmul_rn(e, s), m);
}

// ---------------- prep: code norms ----------------
__global__ void k_prep_n() {
    int j = threadIdx.x;
    float a = 0.f;
    for (int c = 0; c < C_DIM; c++) {
        float v = g_wT[c * NE + j];
        a = fmaf(v, v, a);
    }
    g_n[j] = a;
}

// ---------------- prep: projected codebook pwT[o][j] ----------------
__global__ void k_prep_pw(const float* __restrict__ convw,
                          const float* __restrict__ convb) {
    __shared__ float cw[16][512];   // 32 KB
    int bo = blockIdx.x * 16;       // 16 output channels per block
    for (int p = 0; p < 32; p++) {
        int id = threadIdx.x + p * 256;           // 0..8191
        cw[id >> 9][id & 511] = convw[(size_t)bo * 512 + id];
    }
    __syncthreads();
    int j = threadIdx.x;
    float acc[16];
#pragma unroll
    for (int o = 0; o < 16; o++) acc[o] = 0.f;
    for (int c = 0; c < C_DIM; c++) {
        float wv = g_wT[c * NE + j];
#pragma unroll
        for (int o = 0; o < 16; o++) acc[o] = fmaf(cw[o][c], wv, acc[o]);
    }
#pragma unroll
    for (int o = 0; o < 16; o++)
        g_pwT[(size_t)(bo + o) * NE + j] = __fadd_rn(acc[o], convb[bo + o]);
}

// ---------------- main fused kernel ----------------
// Block: 128 tokens x 256 codes. 512 threads = 16 warps.
// warp ty owns tokens ty*8..ty*8+7; lane tx owns codes {tx*4..tx*4+3, 128+tx*4..+3}.
__global__ __launch_bounds__(512, 1) void k_main(const float* __restrict__ z,
                                                 float* __restrict__ out) {
    __shared__ union SM {
        struct { float zs[2][16][128]; float ws[2][16][256]; } g;   // 49152 B
        struct { float pws[32 * 256]; int idx[128]; float A[128];
                 float dsum[16]; int hist[256]; } p;                // ~35 KB
    } S;

    const int tid = threadIdx.x;
    const int tx = tid & 31, ty = tid >> 5;
    const int b = blockIdx.x >> 5;            // 32 blocks per batch image
    const int hw0 = (blockIdx.x & 31) << 7;   // 128 hw positions
    const float* zb = z + (size_t)b * C_DIM * HW + hw0;

    ull acc[8][4];
#pragma unroll
    for (int t = 0; t < 8; t++)
#pragma unroll
        for (int p = 0; p < 4; p++) acc[t][p] = 0ull;

    float regA = 0.f;   // per-token ||z||^2 partial (threads 0..127)

    // ---- prologue: load stage 0 ----
    float4 pz, pw0, pw1;
    pz  = *(const float4*)(zb + (size_t)ty * HW + tx * 4);
    {
        int id0 = tid, id1 = tid + 512;
        pw0 = *(const float4*)(g_wT + (size_t)(id0 >> 6) * NE + (id0 & 63) * 4);
        pw1 = *(const float4*)(g_wT + (size_t)(id1 >> 6) * NE + (id1 & 63) * 4);
    }
    *(float4*)&S.g.zs[0][ty][tx * 4] = pz;
    {
        int id0 = tid, id1 = tid + 512;
        *(float4*)&S.g.ws[0][id0 >> 6][(id0 & 63) * 4] = pw0;
        *(float4*)&S.g.ws[0][id1 >> 6][(id1 & 63) * 4] = pw1;
    }

    // ---- K loop: 32 stages of Kc=16, double buffered ----
    for (int s = 0; s < 32; s++) {
        int buf = s & 1;
        if (s < 31) {
            int c0 = (s + 1) * 16;
            pz = *(const float4*)(zb + (size_t)(c0 + ty) * HW + tx * 4);
            int id0 = tid, id1 = tid + 512;
            pw0 = *(const float4*)(g_wT + (size_t)(c0 + (id0 >> 6)) * NE + (id0 & 63) * 4);
            pw1 = *(const float4*)(g_wT + (size_t)(c0 + (id1 >> 6)) * NE + (id1 & 63) * 4);
        }
        __syncthreads();
#pragma unroll
        for (int k = 0; k < 16; k++) {
            float4 za = *(const float4*)&S.g.zs[buf][k][ty * 8];
            float4 zc = *(const float4*)&S.g.zs[buf][k][ty * 8 + 4];
            float4 wa = *(const float4*)&S.g.ws[buf][k][tx * 4];
            float4 wb = *(const float4*)&S.g.ws[buf][k][128 + tx * 4];
            ull wp[4];
            wp[0] = pack2(wa.x, wa.y); wp[1] = pack2(wa.z, wa.w);
            wp[2] = pack2(wb.x, wb.y); wp[3] = pack2(wb.z, wb.w);
            float zt[8] = {za.x, za.y, za.z, za.w, zc.x, zc.y, zc.z, zc.w};
#pragma unroll
            for (int t = 0; t < 8; t++) {
                ull zz = pack2(zt[t], zt[t]);
#pragma unroll
                for (int p = 0; p < 4; p++)
                    asm("fma.rn.f32x2 %0, %1, %2, %0;"
                        : "+l"(acc[t][p]) : "l"(zz), "l"(wp[p]));
            }
        }
        if (tid < 128) {   // warps 0-3: accumulate ||z||^2 per token
#pragma unroll
            for (int k = 0; k < 16; k++) {
                float v = S.g.zs[buf][k][tid];
                regA = fmaf(v, v, regA);
            }
        }
        if (s < 31) {
            int nb = buf ^ 1;
            *(float4*)&S.g.zs[nb][ty][tx * 4] = pz;
            int id0 = tid, id1 = tid + 512;
            *(float4*)&S.g.ws[nb][id0 >> 6][(id0 & 63) * 4] = pw0;
            *(float4*)&S.g.ws[nb][id1 >> 6][(id1 & 63) * 4] = pw1;
        }
    }
    __syncthreads();

    // ---- phase 2: argmin + loss + histogram ----
    if (tid < 128) S.p.A[tid] = regA;
    if (tid < 256) S.p.hist[tid] = 0;
    __syncthreads();

    float dloc = 0.f;
#pragma unroll
    for (int t = 0; t < 8; t++) {
        int tok = ty * 8 + t;
        float At = S.p.A[tok];
        float bd = __int_as_float(0x7f800000);  // +inf
        int bi = 0;
#pragma unroll
        for (int p = 0; p < 4; p++) {
            int cb = (p < 2) ? (tx * 4 + 2 * p) : (128 + tx * 4 + 2 * (p - 2));
            float dot0 = __uint_as_float((uint)(acc[t][p] & 0xffffffffull));
            float dot1 = __uint_as_float((uint)(acc[t][p] >> 32));
            // mimic reference: fl(fl(A + n_j) - 2*dot)
            float n0 = __ldg(&g_n[cb]);
            float n1 = __ldg(&g_n[cb + 1]);
            float d0 = __fadd_rn(__fadd_rn(At, n0), -2.0f * dot0);
            float d1 = __fadd_rn(__fadd_rn(At, n1), -2.0f * dot1);
            if (d0 < bd) { bd = d0; bi = cb; }
            if (d1 < bd) { bd = d1; bi = cb + 1; }
        }
#pragma unroll
        for (int off = 16; off > 0; off >>= 1) {
            float od = __shfl_xor_sync(0xffffffffu, bd, off);
            int   oi = __shfl_xor_sync(0xffffffffu, bi, off);
            if (od < bd || (od == bd && oi < bi)) { bd = od; bi = oi; }
        }
        if (tx == 0) {
            S.p.idx[tok] = bi;
            atomicAdd(&S.p.hist[bi], 1);
            dloc += bd;
        }
    }
    if (tx == 0) S.p.dsum[ty] = dloc;
    __syncthreads();
    if (tid == 0) {
        float sum = 0.f;
#pragma unroll
        for (int i = 0; i < 16; i++) sum += S.p.dsum[i];
        g_partial[blockIdx.x] = sum;   // deterministic: direct store per block
    }
    if (tid < 256) atomicAdd(&g_hist[tid], S.p.hist[tid]);  // int atomics: deterministic

    // ---- phase 3: gather projected codebook -> output ----
    const size_t outbase = (size_t)b * C_DIM * HW + hw0;
    for (int ch = 0; ch < 16; ch++) {     // 32 output channels per chunk
        __syncthreads();
#pragma unroll
        for (int p = 0; p < 4; p++) {
            int id = tid + p * 512;       // 0..2047 float4s
            *(float4*)&S.p.pws[(id >> 6) * NE + (id & 63) * 4] =
                *(const float4*)&g_pwT[(size_t)(ch * 32 + (id >> 6)) * NE + (id & 63) * 4];
        }
        __syncthreads();
        int i = tid & 127, og = tid >> 7;
        int mi = S.p.idx[i];
#pragma unroll
        for (int r = 0; r < 8; r++) {
            int ol = og * 8 + r;
            out[outbase + (size_t)(ch * 32 + ol) * HW + i] = S.p.pws[ol * NE + mi];
        }
    }
}

// ---------------- finalize: loss + perplexity ----------------
__global__ void k_fin(float* __restrict__ out, long long osize) {
    if (threadIdx.x == 0) {
        float s = 0.f;
        for (int i = 0; i < NBLK; i++) s += g_partial[i];
        float m = s * (1.0f / 33554432.0f);        // exact power-of-two scale
        out[osize - 2] = __fadd_rn(m, 0.25f * m);  // mean + BETA*mean
        float h = 0.f;
        for (int j = 0; j < NE; j++) {
            float e = (float)g_hist[j] * (1.0f / 65536.0f);
            h += e * logf(e + 1e-10f);
        }
        out[osize - 1] = expf(-h);
    }
}

// ---------------- launch ----------------
extern "C" void kernel_launch(void* const* d_in, const int* in_sizes, int n_in,
                              void* d_out, int out_size) {
    const float* z     = (const float*)d_in[0];
    const float* emb   = (const float*)d_in[1];
    const float* stdp  = (const float*)d_in[2];
    const float* means = (const float*)d_in[3];
    const float* convw = (const float*)d_in[4];
    const float* convb = (const float*)d_in[5];
    float* out = (float*)d_out;

    k_init<<<1, 512>>>();
    k_prep_w<<<512, 256>>>(emb, stdp, means);
    k_prep_n<<<1, 256>>>();
    k_prep_pw<<<32, 256>>>(convw, convb);
    k_main<<<NBLK, 512>>>(z, out);
    k_fin<<<1, 32>>>(out, (long long)out_size);
}